// round 1
// baseline (speedup 1.0000x reference)
#include <cuda_runtime.h>
#include <cuda_bf16.h>
#include <math.h>

#define NN   100000
#define EE   1600000
#define FIN  128
#define HD   256
#define NHID_ 512
#define NOUT_ 256
#define GG   256

// ---------------- scratch (no allocation allowed) ----------------
__device__ float g_t[(size_t)NN * HD];      // GEMM output / SpMM input
__device__ float g_h[(size_t)NN * HD];      // layer activations
__device__ int   g_deg[NN];
__device__ float g_dinv[NN];
__device__ int   g_rowoff[NN + 1];
__device__ int   g_cursor[NN];
__device__ int   g_col[EE];
__device__ int   g_gstart[GG + 1];
__device__ float g_pooled[GG * HD];
__device__ float g_mlp1[GG * NHID_];

// ---------------- CSR construction ----------------
__global__ void zero_deg_kernel() {
    int i = blockIdx.x * blockDim.x + threadIdx.x;
    if (i < NN) g_deg[i] = 0;
}

__global__ void count_kernel(const int* __restrict__ dst) {
    int e = blockIdx.x * blockDim.x + threadIdx.x;
    if (e < EE) atomicAdd(&g_deg[dst[e]], 1);
}

// single-block exclusive scan of g_deg -> g_rowoff, g_cursor
__global__ void scan_kernel() {
    __shared__ int sh[1024];
    __shared__ int carry;
    int tid = threadIdx.x;
    if (tid == 0) carry = 0;
    __syncthreads();
    for (int base = 0; base < NN; base += 1024) {
        int i = base + tid;
        int v = (i < NN) ? g_deg[i] : 0;
        sh[tid] = v;
        __syncthreads();
        for (int off = 1; off < 1024; off <<= 1) {
            int t = (tid >= off) ? sh[tid - off] : 0;
            __syncthreads();
            sh[tid] += t;
            __syncthreads();
        }
        int excl = carry + sh[tid] - v;
        if (i < NN) { g_rowoff[i] = excl; g_cursor[i] = excl; }
        __syncthreads();
        if (tid == 1023) carry += sh[1023];
        __syncthreads();
    }
    if (tid == 0) g_rowoff[NN] = carry;
}

__global__ void dinv_kernel() {
    int i = blockIdx.x * blockDim.x + threadIdx.x;
    if (i < NN) g_dinv[i] = rsqrtf(1.0f + (float)g_deg[i]);
}

__global__ void scatter_kernel(const int* __restrict__ src, const int* __restrict__ dst) {
    int e = blockIdx.x * blockDim.x + threadIdx.x;
    if (e < EE) {
        int p = atomicAdd(&g_cursor[dst[e]], 1);
        g_col[p] = src[e];
    }
}

// ---------------- SGEMM: C[M,N] = A[M,K] @ B[K,N] (+bias)(+relu) ----------------
// BM=BN=128, BK=8, 256 threads, 8x8 per thread. Requires K%8==0, N%128==0.
template <bool BIAS, bool RELU>
__global__ void __launch_bounds__(256)
sgemm_kernel(const float* __restrict__ A, const float* __restrict__ B,
             const float* __restrict__ bias, float* __restrict__ C,
             int M, int K, int N) {
    __shared__ float As[8][128];
    __shared__ float Bs[8][128];
    const int tid = threadIdx.x;
    const int m0 = blockIdx.y * 128;
    const int n0 = blockIdx.x * 128;

    const int arow = tid >> 1;
    const int acol = (tid & 1) * 4;
    const int bkrow = tid >> 5;
    const int bcol = (tid & 31) * 4;

    const int ty = tid >> 4;   // 0..15
    const int tx = tid & 15;   // 0..15

    float acc[8][8];
#pragma unroll
    for (int i = 0; i < 8; i++)
#pragma unroll
        for (int j = 0; j < 8; j++) acc[i][j] = 0.0f;

    for (int k0 = 0; k0 < K; k0 += 8) {
        // load A tile (128x8), transposed into As[k][m]; guard rows
        float4 av = make_float4(0.f, 0.f, 0.f, 0.f);
        int gr = m0 + arow;
        if (gr < M) av = *(const float4*)(A + (size_t)gr * K + k0 + acol);
        As[acol + 0][arow] = av.x;
        As[acol + 1][arow] = av.y;
        As[acol + 2][arow] = av.z;
        As[acol + 3][arow] = av.w;
        // load B tile (8x128)
        float4 bv = *(const float4*)(B + (size_t)(k0 + bkrow) * N + n0 + bcol);
        *(float4*)&Bs[bkrow][bcol] = bv;
        __syncthreads();

#pragma unroll
        for (int kk = 0; kk < 8; kk++) {
            float ar[8], br[8];
            float4 a0 = *(const float4*)&As[kk][ty * 8];
            float4 a1 = *(const float4*)&As[kk][ty * 8 + 4];
            float4 b0 = *(const float4*)&Bs[kk][tx * 8];
            float4 b1 = *(const float4*)&Bs[kk][tx * 8 + 4];
            ar[0] = a0.x; ar[1] = a0.y; ar[2] = a0.z; ar[3] = a0.w;
            ar[4] = a1.x; ar[5] = a1.y; ar[6] = a1.z; ar[7] = a1.w;
            br[0] = b0.x; br[1] = b0.y; br[2] = b0.z; br[3] = b0.w;
            br[4] = b1.x; br[5] = b1.y; br[6] = b1.z; br[7] = b1.w;
#pragma unroll
            for (int i = 0; i < 8; i++)
#pragma unroll
                for (int j = 0; j < 8; j++)
                    acc[i][j] = fmaf(ar[i], br[j], acc[i][j]);
        }
        __syncthreads();
    }

#pragma unroll
    for (int i = 0; i < 8; i++) {
        int row = m0 + ty * 8 + i;
        if (row >= M) continue;
#pragma unroll
        for (int j = 0; j < 8; j++) {
            int colc = n0 + tx * 8 + j;
            float v = acc[i][j];
            if (BIAS) v += bias[colc];
            if (RELU) v = fmaxf(v, 0.0f);
            C[(size_t)row * N + colc] = v;
        }
    }
}

// ---------------- SpMM (CSR by dst) + self-loop + bias (+relu) ----------------
// 4 nodes per 256-thread block; 64 threads (one float4 each) per node's 256-wide row.
template <bool RELU>
__global__ void __launch_bounds__(256)
spmm_kernel(const float* __restrict__ Hin, const float* __restrict__ bias,
            float* __restrict__ Hout) {
    int node = blockIdx.x * 4 + (threadIdx.x >> 6);
    if (node >= NN) return;
    int lane = threadIdx.x & 63;
    float di = g_dinv[node];
    const float4* hp = (const float4*)Hin;

    float4 a = hp[(size_t)node * 64 + lane];
    float w0 = di * di;
    float4 acc = make_float4(a.x * w0, a.y * w0, a.z * w0, a.w * w0);

    int s = g_rowoff[node];
    int e = g_rowoff[node + 1];
    for (int p = s; p < e; p++) {
        int j = g_col[p];
        float wj = di * g_dinv[j];
        float4 v = hp[(size_t)j * 64 + lane];
        acc.x = fmaf(wj, v.x, acc.x);
        acc.y = fmaf(wj, v.y, acc.y);
        acc.z = fmaf(wj, v.z, acc.z);
        acc.w = fmaf(wj, v.w, acc.w);
    }
    float4 b = ((const float4*)bias)[lane];
    acc.x += b.x; acc.y += b.y; acc.z += b.z; acc.w += b.w;
    if (RELU) {
        acc.x = fmaxf(acc.x, 0.f); acc.y = fmaxf(acc.y, 0.f);
        acc.z = fmaxf(acc.z, 0.f); acc.w = fmaxf(acc.w, 0.f);
    }
    ((float4*)Hout)[(size_t)node * 64 + lane] = acc;
}

// ---------------- pooling (batch is sorted) ----------------
__global__ void bounds_kernel(const int* __restrict__ batch) {
    int i = blockIdx.x * blockDim.x + threadIdx.x;
    if (i >= NN) return;
    int b = batch[i];
    int prev = (i == 0) ? -1 : batch[i - 1];
    for (int g = prev + 1; g <= b; g++) g_gstart[g] = i;
    if (i == NN - 1)
        for (int g = b + 1; g <= GG; g++) g_gstart[g] = NN;
}

__global__ void pool_kernel(const float* __restrict__ H) {
    int g = blockIdx.x;       // 256 graphs
    int c = threadIdx.x;      // 256 channels
    int s = g_gstart[g];
    int e = g_gstart[g + 1];
    float acc = 0.0f;
    for (int i = s; i < e; i++) acc += H[(size_t)i * HD + c];
    float cnt = (float)(e - s);
    if (cnt < 1.0f) cnt = 1.0f;
    g_pooled[g * HD + c] = acc / cnt;
}

// ---------------- launch ----------------
extern "C" void kernel_launch(void* const* d_in, const int* in_sizes, int n_in,
                              void* d_out, int out_size) {
    const float* x     = (const float*)d_in[0];
    const int*   src   = (const int*)d_in[1];
    const int*   dst   = (const int*)d_in[2];
    const int*   batch = (const int*)d_in[3];
    const float* W1 = (const float*)d_in[4];
    const float* b1 = (const float*)d_in[5];
    const float* W2 = (const float*)d_in[6];
    const float* b2 = (const float*)d_in[7];
    const float* W3 = (const float*)d_in[8];
    const float* b3 = (const float*)d_in[9];
    const float* Wm1 = (const float*)d_in[10];
    const float* bm1 = (const float*)d_in[11];
    const float* Wm2 = (const float*)d_in[12];
    const float* bm2 = (const float*)d_in[13];
    float* out = (float*)d_out;

    float *t, *h, *pooled, *mlp1;
    cudaGetSymbolAddress((void**)&t, g_t);
    cudaGetSymbolAddress((void**)&h, g_h);
    cudaGetSymbolAddress((void**)&pooled, g_pooled);
    cudaGetSymbolAddress((void**)&mlp1, g_mlp1);

    const int TB = 256;
    // ----- CSR + degrees -----
    zero_deg_kernel<<<(NN + TB - 1) / TB, TB>>>();
    count_kernel<<<(EE + TB - 1) / TB, TB>>>(dst);
    scan_kernel<<<1, 1024>>>();
    dinv_kernel<<<(NN + TB - 1) / TB, TB>>>();
    scatter_kernel<<<(EE + TB - 1) / TB, TB>>>(src, dst);

    dim3 gemm_grid_l1(HD / 128, (NN + 127) / 128);
    dim3 gemm_grid_l23(HD / 128, (NN + 127) / 128);
    int spmm_grid = (NN + 3) / 4;

    // ----- layer 1: t = x @ W1 ; h = relu(agg(t) + b1) -----
    sgemm_kernel<false, false><<<gemm_grid_l1, 256>>>(x, W1, nullptr, t, NN, FIN, HD);
    spmm_kernel<true><<<spmm_grid, 256>>>(t, b1, h);
    // ----- layer 2 -----
    sgemm_kernel<false, false><<<gemm_grid_l23, 256>>>(h, W2, nullptr, t, NN, HD, HD);
    spmm_kernel<true><<<spmm_grid, 256>>>(t, b2, h);
    // ----- layer 3 (no relu) -----
    sgemm_kernel<false, false><<<gemm_grid_l23, 256>>>(h, W3, nullptr, t, NN, HD, HD);
    spmm_kernel<false><<<spmm_grid, 256>>>(t, b3, h);

    // ----- pooling -----
    bounds_kernel<<<(NN + TB - 1) / TB, TB>>>(batch);
    pool_kernel<<<GG, HD>>>(h);

    // ----- MLP head -----
    dim3 mlp1_grid(NHID_ / 128, (GG + 127) / 128);
    sgemm_kernel<true, true><<<mlp1_grid, 256>>>(pooled, Wm1, bm1, mlp1, GG, HD, NHID_);
    dim3 mlp2_grid(NOUT_ / 128, (GG + 127) / 128);
    sgemm_kernel<true, false><<<mlp2_grid, 256>>>(mlp1, Wm2, bm2, out, GG, NHID_, NOUT_);
}